// round 7
// baseline (speedup 1.0000x reference)
#include <cuda_runtime.h>
#include <math.h>

#define N_NODES_MAX 50000
#define N_EDGES_MAX 800000
#define D 64
#define N_REL 8

__device__ float g_agg[(size_t)N_NODES_MAX * D];   // 12.8 MB (written, not RMW)
__device__ float g_cnt[N_NODES_MAX];
__device__ float g_w[N_REL * 2 * D];               // w = W_r.sum(-1)
__device__ float g_y[(size_t)N_NODES_MAX * 16];    // y tables
__device__ int   g_off[N_NODES_MAX + 1];           // CSR offsets (counts then scanned)
__device__ int   g_cur[N_NODES_MAX];               // write cursors
__device__ unsigned g_esrc[N_EDGES_MAX];           // sorted-by-dst: src id
__device__ float    g_egate[N_EDGES_MAX];          // sorted-by-dst: gate

// ---------------------------------------------------------------------------
// Kernel 1: w[r][j] = sum_k W_r[r][j][k]
// ---------------------------------------------------------------------------
__global__ void wsum_kernel(const float* __restrict__ W_r) {
    int r = blockIdx.x;
    int j = threadIdx.x;
    const float4* row = (const float4*)(W_r + ((size_t)r * 2 * D + j) * D);
    float4 s = make_float4(0.f, 0.f, 0.f, 0.f);
#pragma unroll
    for (int k = 0; k < D / 4; k++) {
        float4 v = __ldg(row + k);
        s.x += v.x; s.y += v.y; s.z += v.z; s.w += v.w;
    }
    g_w[r * 2 * D + j] = (s.x + s.y) + (s.z + s.w);
}

// ---------------------------------------------------------------------------
// Kernel 1b: y tables.  y[n][j] = <x[n], w[j][0:64]>,  y[n][8+j] = <x[n], w[j][64:128]>
// ---------------------------------------------------------------------------
__global__ __launch_bounds__(256) void y_kernel(const float* __restrict__ x, int N) {
    __shared__ float xt[D][17];
    __shared__ float wt[D][16];

    int tid = threadIdx.x;
    int base = blockIdx.x * 16;

#pragma unroll
    for (int q = 0; q < 4; q++) {
        int idx = tid + q * 256;
        int k = idx >> 4, j = idx & 15;
        wt[k][j] = (j < 8) ? g_w[j * 2 * D + k] : g_w[(j - 8) * 2 * D + D + k];
    }
    {
        int n = tid >> 4;
        int k0 = (tid & 15) * 4;
        int nn = min(base + n, N - 1);
        float4 v = __ldg((const float4*)(x + (size_t)nn * D + k0));
        xt[k0 + 0][n] = v.x; xt[k0 + 1][n] = v.y;
        xt[k0 + 2][n] = v.z; xt[k0 + 3][n] = v.w;
    }
    __syncthreads();

    int n = tid & 15, j = tid >> 4;
    float acc = 0.f;
#pragma unroll
    for (int k = 0; k < D; k++) acc += xt[k][n] * wt[k][j];

    int nn = base + n;
    if (nn < N) g_y[(size_t)nn * 16 + j] = acc;
}

// ---------------------------------------------------------------------------
// CSR build step A: zero counts
// ---------------------------------------------------------------------------
__global__ void zero_off_kernel(int N) {
    int i = blockIdx.x * blockDim.x + threadIdx.x;
    if (i <= N) g_off[i] = 0;
}

// CSR build step B: histogram of dst (counts at g_off[d+1])
__global__ void hist_kernel(const int* __restrict__ dst, int E) {
    int e = blockIdx.x * blockDim.x + threadIdx.x;
    if (e < E) atomicAdd(&g_off[__ldg(dst + e) + 1], 1);
}

// CSR build step C: single-block inclusive scan over g_off[0..N];
// also initializes g_cur[n] = start offset of node n.
__global__ __launch_bounds__(1024) void scan_kernel(int N) {
    __shared__ int part[1024];
    int n = N + 1;
    int tid = threadIdx.x;
    int CH = (n + 1023) / 1024;
    int beg = tid * CH;
    int end = min(beg + CH, n);

    int sum = 0;
    for (int i = beg; i < end; i++) sum += g_off[i];
    part[tid] = sum;
    __syncthreads();

    for (int ofs = 1; ofs < 1024; ofs <<= 1) {
        int v = (tid >= ofs) ? part[tid - ofs] : 0;
        __syncthreads();
        part[tid] += v;
        __syncthreads();
    }

    int run = (tid > 0) ? part[tid - 1] : 0;
    for (int i = beg; i < end; i++) {
        run += g_off[i];
        g_off[i] = run;            // inclusive: g_off[i] = start offset of node i
        if (i < N) g_cur[i] = run; // cursor starts at node i's offset
    }
}

// ---------------------------------------------------------------------------
// Pass 1: gate + scatter into dst-sorted slots. One thread per edge.
// ---------------------------------------------------------------------------
__global__ __launch_bounds__(256) void gate_scatter_kernel(
        const int* __restrict__ src,
        const int* __restrict__ dst,
        const int* __restrict__ rel,
        int E) {
    int e = blockIdx.x * blockDim.x + threadIdx.x;
    if (e >= E) return;

    int s = __ldg(src + e);
    int d = __ldg(dst + e);
    int r = __ldg(rel + e);

    float yd = __ldg(g_y + (size_t)d * 16 + r);
    float ys = __ldg(g_y + (size_t)s * 16 + 8 + r);
    float gate = 1.0f / (1.0f + __expf(-(yd + ys)));

    int pos = atomicAdd(&g_cur[d], 1);
    g_esrc[pos] = (unsigned)s;
    g_egate[pos] = gate;
}

// ---------------------------------------------------------------------------
// Pass 2: gather-accumulate. Half-warp per dst node; 4-edge batched inner loop.
// Writes agg[n] once (coalesced float4) and cnt[n]. No atomics, no pre-zero.
// ---------------------------------------------------------------------------
__global__ __launch_bounds__(256) void gather_kernel(const float* __restrict__ x, int N) {
    int warp = (blockIdx.x * blockDim.x + threadIdx.x) >> 5;
    int lane = threadIdx.x & 31;
    int half = lane >> 4;
    int sub  = lane & 15;

    int n = warp * 2 + half;
    if (n >= N) return;

    int e0 = __ldg(g_off + n);
    int e1 = __ldg(g_off + n + 1);

    const float4* x4 = (const float4*)x;
    float4 acc = make_float4(0.f, 0.f, 0.f, 0.f);

    int e = e0;
    for (; e + 4 <= e1; e += 4) {
        unsigned s0 = __ldg(g_esrc + e + 0);
        unsigned s1 = __ldg(g_esrc + e + 1);
        unsigned s2 = __ldg(g_esrc + e + 2);
        unsigned s3 = __ldg(g_esrc + e + 3);
        float g0 = __ldg(g_egate + e + 0);
        float g1 = __ldg(g_egate + e + 1);
        float g2 = __ldg(g_egate + e + 2);
        float g3 = __ldg(g_egate + e + 3);
        float4 v0 = __ldg(x4 + (size_t)s0 * (D / 4) + sub);
        float4 v1 = __ldg(x4 + (size_t)s1 * (D / 4) + sub);
        float4 v2 = __ldg(x4 + (size_t)s2 * (D / 4) + sub);
        float4 v3 = __ldg(x4 + (size_t)s3 * (D / 4) + sub);
        acc.x += g0 * v0.x + g1 * v1.x + g2 * v2.x + g3 * v3.x;
        acc.y += g0 * v0.y + g1 * v1.y + g2 * v2.y + g3 * v3.y;
        acc.z += g0 * v0.z + g1 * v1.z + g2 * v2.z + g3 * v3.z;
        acc.w += g0 * v0.w + g1 * v1.w + g2 * v2.w + g3 * v3.w;
    }
    for (; e < e1; e++) {
        unsigned s0 = __ldg(g_esrc + e);
        float g0 = __ldg(g_egate + e);
        float4 v0 = __ldg(x4 + (size_t)s0 * (D / 4) + sub);
        acc.x += g0 * v0.x; acc.y += g0 * v0.y;
        acc.z += g0 * v0.z; acc.w += g0 * v0.w;
    }

    *(float4*)(g_agg + (size_t)n * D + sub * 4) = acc;
    if (sub == 0) g_cnt[n] = (float)(e1 - e0);
}

// ---------------------------------------------------------------------------
// Kernel 4: node GEMM (unchanged from R5).
// ---------------------------------------------------------------------------
#define BN 64
#define KCH 64

__global__ __launch_bounds__(256, 3) void node_kernel(
        const float* __restrict__ x,
        const float* __restrict__ Wl,
        const float* __restrict__ b,
        float* __restrict__ out,
        int N) {
    __shared__ float csm[KCH][66];
    __shared__ float wsm[D][KCH];

    int tid = threadIdx.x;
    int tx = tid & 31;
    int ty = tid >> 5;
    int base = blockIdx.x * BN;

    float acc[2][8];
#pragma unroll
    for (int j = 0; j < 8; j++) {
        float bv = __ldg(b + ty * 8 + j);
        acc[0][j] = bv; acc[1][j] = bv;
    }

#pragma unroll
    for (int kc = 0; kc < 2; kc++) {
#pragma unroll
        for (int q = 0; q < 4; q++) {
            int idx = (tid + q * 256) * 4;
            int o = idx >> 6, k = idx & 63;
            float4 v = __ldg((const float4*)(Wl + (size_t)o * 2 * D + kc * KCH + k));
            *(float4*)&wsm[o][k] = v;
        }
        {
            int n = tid & 63;
            int q16 = tid >> 6;
            int k0 = q16 * 16;
            int nn = min(base + n, N - 1);
            const float4* srcp;
            float scale;
            if (kc == 0) {
                srcp = (const float4*)(x + (size_t)nn * D + k0);
                scale = 1.0f;
            } else {
                srcp = (const float4*)(g_agg + (size_t)nn * D + k0);
                scale = 1.0f / fmaxf(g_cnt[nn], 1.0f);
            }
#pragma unroll
            for (int q = 0; q < 4; q++) {
                float4 v = __ldg(srcp + q);
                int k = k0 + q * 4;
                csm[k + 0][n] = v.x * scale;
                csm[k + 1][n] = v.y * scale;
                csm[k + 2][n] = v.z * scale;
                csm[k + 3][n] = v.w * scale;
            }
        }
        __syncthreads();

#pragma unroll 8
        for (int k4 = 0; k4 < KCH; k4 += 4) {
            float4 w[8];
#pragma unroll
            for (int j = 0; j < 8; j++)
                w[j] = *(const float4*)&wsm[ty * 8 + j][k4];

            float2 c0 = *(const float2*)&csm[k4 + 0][tx * 2];
            float2 c1 = *(const float2*)&csm[k4 + 1][tx * 2];
            float2 c2 = *(const float2*)&csm[k4 + 2][tx * 2];
            float2 c3 = *(const float2*)&csm[k4 + 3][tx * 2];

#pragma unroll
            for (int j = 0; j < 8; j++) {
                acc[0][j] += c0.x * w[j].x; acc[1][j] += c0.y * w[j].x;
                acc[0][j] += c1.x * w[j].y; acc[1][j] += c1.y * w[j].y;
                acc[0][j] += c2.x * w[j].z; acc[1][j] += c2.y * w[j].z;
                acc[0][j] += c3.x * w[j].w; acc[1][j] += c3.y * w[j].w;
            }
        }
        __syncthreads();
    }

#pragma unroll
    for (int i = 0; i < 2; i++) {
        int n = base + tx * 2 + i;
        if (n < N) {
            float* op = out + (size_t)n * D + ty * 8;
            float4 r0, r1;
            r0.x = acc[i][0] > 0.f ? acc[i][0] : 0.01f * acc[i][0];
            r0.y = acc[i][1] > 0.f ? acc[i][1] : 0.01f * acc[i][1];
            r0.z = acc[i][2] > 0.f ? acc[i][2] : 0.01f * acc[i][2];
            r0.w = acc[i][3] > 0.f ? acc[i][3] : 0.01f * acc[i][3];
            r1.x = acc[i][4] > 0.f ? acc[i][4] : 0.01f * acc[i][4];
            r1.y = acc[i][5] > 0.f ? acc[i][5] : 0.01f * acc[i][5];
            r1.z = acc[i][6] > 0.f ? acc[i][6] : 0.01f * acc[i][6];
            r1.w = acc[i][7] > 0.f ? acc[i][7] : 0.01f * acc[i][7];
            *(float4*)op = r0;
            *(float4*)(op + 4) = r1;
        }
    }
}

// ---------------------------------------------------------------------------
extern "C" void kernel_launch(void* const* d_in, const int* in_sizes, int n_in,
                              void* d_out, int out_size) {
    const float* x    = (const float*)d_in[0];
    const int*   src  = (const int*)d_in[1];
    const int*   dst  = (const int*)d_in[2];
    const int*   rel  = (const int*)d_in[3];
    const float* W_r  = (const float*)d_in[4];
    const float* W_lin= (const float*)d_in[5];
    const float* b_lin= (const float*)d_in[6];
    float* out = (float*)d_out;

    int N = in_sizes[0] / D;     // 50000
    int E = in_sizes[1];         // 800000

    wsum_kernel<<<N_REL, 2 * D>>>(W_r);
    y_kernel<<<(N + 15) / 16, 256>>>(x, N);

    zero_off_kernel<<<(N + 256) / 256, 256>>>(N);
    hist_kernel<<<(E + 255) / 256, 256>>>(dst, E);
    scan_kernel<<<1, 1024>>>(N);
    gate_scatter_kernel<<<(E + 255) / 256, 256>>>(src, dst, rel, E);

    int gwarps = (N + 1) / 2;
    gather_kernel<<<(gwarps * 32 + 255) / 256, 256>>>(x, N);

    node_kernel<<<(N + BN - 1) / BN, 256>>>(x, W_lin, b_lin, out, N);
}

// round 10
// speedup vs baseline: 1.6080x; 1.6080x over previous
#include <cuda_runtime.h>
#include <math.h>

#define N_NODES_MAX 50000
#define D 64
#define N_REL 8

__device__ float g_agg[(size_t)N_NODES_MAX * D];   // 12.8 MB
__device__ float g_cnt[N_NODES_MAX];
__device__ float g_w[N_REL * 2 * D];               // w = W_r.sum(-1)
__device__ float g_y[(size_t)N_NODES_MAX * 16];    // y tables

// ---------------------------------------------------------------------------
// Kernel 1: w[r][j] = sum_k W_r[r][j][k]
// ---------------------------------------------------------------------------
__global__ void wsum_kernel(const float* __restrict__ W_r) {
    int r = blockIdx.x;
    int j = threadIdx.x;
    const float4* row = (const float4*)(W_r + ((size_t)r * 2 * D + j) * D);
    float4 s = make_float4(0.f, 0.f, 0.f, 0.f);
#pragma unroll
    for (int k = 0; k < D / 4; k++) {
        float4 v = __ldg(row + k);
        s.x += v.x; s.y += v.y; s.z += v.z; s.w += v.w;
    }
    g_w[r * 2 * D + j] = (s.x + s.y) + (s.z + s.w);
}

// ---------------------------------------------------------------------------
// Kernel 1b: y tables + fused scratch zeroing.
//   y[n][j]   = <x[n], w[j][0:64]>   j=0..7
//   y[n][8+j] = <x[n], w[j][64:128]>
// Each block also zeroes its grid-stride slice of g_agg / g_cnt (needed by
// the RED-based edge kernel; fusing removes a separate launch).
// ---------------------------------------------------------------------------
__global__ __launch_bounds__(256) void y_kernel(const float* __restrict__ x, int N) {
    __shared__ float xt[D][17];
    __shared__ float wt[D][16];

    int tid = threadIdx.x;
    int base = blockIdx.x * 16;

    // fused zeroing (independent of the y computation; overlaps with it)
    {
        int gidx = blockIdx.x * blockDim.x + tid;
        int n_agg4 = N * (D / 4);
        int stride = gridDim.x * blockDim.x;
        for (int i = gidx; i < n_agg4; i += stride)
            ((float4*)g_agg)[i] = make_float4(0.f, 0.f, 0.f, 0.f);
        for (int i = gidx; i < N; i += stride)
            g_cnt[i] = 0.f;
    }

#pragma unroll
    for (int q = 0; q < 4; q++) {
        int idx = tid + q * 256;
        int k = idx >> 4, j = idx & 15;
        wt[k][j] = (j < 8) ? g_w[j * 2 * D + k] : g_w[(j - 8) * 2 * D + D + k];
    }
    {
        int n = tid >> 4;
        int k0 = (tid & 15) * 4;
        int nn = min(base + n, N - 1);
        float4 v = __ldg((const float4*)(x + (size_t)nn * D + k0));
        xt[k0 + 0][n] = v.x; xt[k0 + 1][n] = v.y;
        xt[k0 + 2][n] = v.z; xt[k0 + 3][n] = v.w;
    }
    __syncthreads();

    int n = tid & 15, j = tid >> 4;
    float acc = 0.f;
#pragma unroll
    for (int k = 0; k < D; k++) acc += xt[k][n] * wt[k][j];

    int nn = base + n;
    if (nn < N) g_y[(size_t)nn * 16 + j] = acc;
}

// ---------------------------------------------------------------------------
// Kernel 3: edge phase, BATCHED (EB=8). Half-warp handles 8 edges; all loads
// front-issued (~24 outstanding/thread) before any dependent compute/red.
//   gate = sigmoid(y[dst][rel] + y[src][8+rel])
//   red.global.add.v4  agg[dst] += x[src]*gate ;  cnt[dst] += 1
// ---------------------------------------------------------------------------
#define EB 8

__global__ __launch_bounds__(256) void edge_kernel(
        const float* __restrict__ x,
        const int* __restrict__ src,
        const int* __restrict__ dst,
        const int* __restrict__ rel,
        int E) {
    int gw = (blockIdx.x * blockDim.x + threadIdx.x) >> 5;
    int lane = threadIdx.x & 31;
    int half = lane >> 4;
    int sub  = lane & 15;

    int base = (gw * 2 + half) * EB;
    if (base >= E) return;

    int s[EB], d[EB], r[EB];
#pragma unroll
    for (int i = 0; i < EB; i++) {
        int e = min(base + i, E - 1);
        s[i] = __ldg(src + e);
        d[i] = __ldg(dst + e);
        r[i] = __ldg(rel + e);
    }

    float yd[EB], ys[EB];
#pragma unroll
    for (int i = 0; i < EB; i++) {
        yd[i] = __ldg(g_y + (size_t)d[i] * 16 + r[i]);
        ys[i] = __ldg(g_y + (size_t)s[i] * 16 + 8 + r[i]);
    }

    float4 xs[EB];
#pragma unroll
    for (int i = 0; i < EB; i++)
        xs[i] = __ldg((const float4*)x + (size_t)s[i] * (D / 4) + sub);

#pragma unroll
    for (int i = 0; i < EB; i++) {
        if (base + i < E) {
            float gate = 1.0f / (1.0f + __expf(-(yd[i] + ys[i])));
            float* addr = g_agg + (size_t)d[i] * D + sub * 4;
            asm volatile("red.global.add.v4.f32 [%0], {%1,%2,%3,%4};"
                         :: "l"(addr), "f"(xs[i].x * gate), "f"(xs[i].y * gate),
                            "f"(xs[i].z * gate), "f"(xs[i].w * gate)
                         : "memory");
            if (sub == 0) atomicAdd(g_cnt + d[i], 1.0f);
        }
    }
}

// ---------------------------------------------------------------------------
// Kernel 4: node GEMM. K in two 64-wide chunks; 64 nodes x 64 outs per block;
// thread: 2 nodes x 8 outs. csm[k][node] pad 66; wsm[o][k] broadcast reads.
// ---------------------------------------------------------------------------
#define BN 64
#define KCH 64

__global__ __launch_bounds__(256, 3) void node_kernel(
        const float* __restrict__ x,
        const float* __restrict__ Wl,
        const float* __restrict__ b,
        float* __restrict__ out,
        int N) {
    __shared__ float csm[KCH][66];
    __shared__ float wsm[D][KCH];

    int tid = threadIdx.x;
    int tx = tid & 31;
    int ty = tid >> 5;
    int base = blockIdx.x * BN;

    float acc[2][8];
#pragma unroll
    for (int j = 0; j < 8; j++) {
        float bv = __ldg(b + ty * 8 + j);
        acc[0][j] = bv; acc[1][j] = bv;
    }

#pragma unroll
    for (int kc = 0; kc < 2; kc++) {
#pragma unroll
        for (int q = 0; q < 4; q++) {
            int idx = (tid + q * 256) * 4;
            int o = idx >> 6, k = idx & 63;
            float4 v = __ldg((const float4*)(Wl + (size_t)o * 2 * D + kc * KCH + k));
            *(float4*)&wsm[o][k] = v;
        }
        {
            int n = tid & 63;
            int q16 = tid >> 6;
            int k0 = q16 * 16;
            int nn = min(base + n, N - 1);
            const float4* srcp;
            float scale;
            if (kc == 0) {
                srcp = (const float4*)(x + (size_t)nn * D + k0);
                scale = 1.0f;
            } else {
                srcp = (const float4*)(g_agg + (size_t)nn * D + k0);
                scale = 1.0f / fmaxf(g_cnt[nn], 1.0f);
            }
#pragma unroll
            for (int q = 0; q < 4; q++) {
                float4 v = __ldg(srcp + q);
                int k = k0 + q * 4;
                csm[k + 0][n] = v.x * scale;
                csm[k + 1][n] = v.y * scale;
                csm[k + 2][n] = v.z * scale;
                csm[k + 3][n] = v.w * scale;
            }
        }
        __syncthreads();

#pragma unroll 8
        for (int k4 = 0; k4 < KCH; k4 += 4) {
            float4 w[8];
#pragma unroll
            for (int j = 0; j < 8; j++)
                w[j] = *(const float4*)&wsm[ty * 8 + j][k4];

            float2 c0 = *(const float2*)&csm[k4 + 0][tx * 2];
            float2 c1 = *(const float2*)&csm[k4 + 1][tx * 2];
            float2 c2 = *(const float2*)&csm[k4 + 2][tx * 2];
            float2 c3 = *(const float2*)&csm[k4 + 3][tx * 2];

#pragma unroll
            for (int j = 0; j < 8; j++) {
                acc[0][j] += c0.x * w[j].x; acc[1][j] += c0.y * w[j].x;
                acc[0][j] += c1.x * w[j].y; acc[1][j] += c1.y * w[j].y;
                acc[0][j] += c2.x * w[j].z; acc[1][j] += c2.y * w[j].z;
                acc[0][j] += c3.x * w[j].w; acc[1][j] += c3.y * w[j].w;
            }
        }
        __syncthreads();
    }

#pragma unroll
    for (int i = 0; i < 2; i++) {
        int n = base + tx * 2 + i;
        if (n < N) {
            float* op = out + (size_t)n * D + ty * 8;
            float4 r0, r1;
            r0.x = acc[i][0] > 0.f ? acc[i][0] : 0.01f * acc[i][0];
            r0.y = acc[i][1] > 0.f ? acc[i][1] : 0.01f * acc[i][1];
            r0.z = acc[i][2] > 0.f ? acc[i][2] : 0.01f * acc[i][2];
            r0.w = acc[i][3] > 0.f ? acc[i][3] : 0.01f * acc[i][3];
            r1.x = acc[i][4] > 0.f ? acc[i][4] : 0.01f * acc[i][4];
            r1.y = acc[i][5] > 0.f ? acc[i][5] : 0.01f * acc[i][5];
            r1.z = acc[i][6] > 0.f ? acc[i][6] : 0.01f * acc[i][6];
            r1.w = acc[i][7] > 0.f ? acc[i][7] : 0.01f * acc[i][7];
            *(float4*)op = r0;
            *(float4*)(op + 4) = r1;
        }
    }
}

// ---------------------------------------------------------------------------
extern "C" void kernel_launch(void* const* d_in, const int* in_sizes, int n_in,
                              void* d_out, int out_size) {
    const float* x    = (const float*)d_in[0];
    const int*   src  = (const int*)d_in[1];
    const int*   dst  = (const int*)d_in[2];
    const int*   rel  = (const int*)d_in[3];
    const float* W_r  = (const float*)d_in[4];
    const float* W_lin= (const float*)d_in[5];
    const float* b_lin= (const float*)d_in[6];
    float* out = (float*)d_out;

    int N = in_sizes[0] / D;     // 50000
    int E = in_sizes[1];         // 800000

    wsum_kernel<<<N_REL, 2 * D>>>(W_r);

    // y tables + fused zeroing of agg/cnt
    y_kernel<<<(N + 15) / 16, 256>>>(x, N);

    int halves = (E + EB - 1) / EB;
    int warps = (halves + 1) / 2;
    int ethreads = warps * 32;
    edge_kernel<<<(ethreads + 255) / 256, 256>>>(x, src, dst, rel, E);

    node_kernel<<<(N + BN - 1) / BN, 256>>>(x, W_lin, b_lin, out, N);
}

// round 11
// speedup vs baseline: 1.6393x; 1.0195x over previous
#include <cuda_runtime.h>
#include <math.h>

#define N_NODES_MAX 50000
#define D 64
#define N_REL 8

__device__ float g_agg[(size_t)N_NODES_MAX * D];   // 12.8 MB
__device__ float g_cnt[N_NODES_MAX];
__device__ float g_w[N_REL * 2 * D];               // w = W_r.sum(-1)
__device__ float g_y[(size_t)N_NODES_MAX * 16];    // y tables

// ---------------------------------------------------------------------------
// Kernel 1: w[r][j] = sum_k W_r[r][j][k]
// ---------------------------------------------------------------------------
__global__ void wsum_kernel(const float* __restrict__ W_r) {
    int r = blockIdx.x;
    int j = threadIdx.x;
    const float4* row = (const float4*)(W_r + ((size_t)r * 2 * D + j) * D);
    float4 s = make_float4(0.f, 0.f, 0.f, 0.f);
#pragma unroll
    for (int k = 0; k < D / 4; k++) {
        float4 v = __ldg(row + k);
        s.x += v.x; s.y += v.y; s.z += v.z; s.w += v.w;
    }
    g_w[r * 2 * D + j] = (s.x + s.y) + (s.z + s.w);
}

// ---------------------------------------------------------------------------
// Kernel 1b: y tables + fused scratch zeroing.
// ---------------------------------------------------------------------------
__global__ __launch_bounds__(256) void y_kernel(const float* __restrict__ x, int N) {
    __shared__ float xt[D][17];
    __shared__ float wt[D][16];

    int tid = threadIdx.x;
    int base = blockIdx.x * 16;

    // fused zeroing (independent work; overlaps with y computation)
    {
        int gidx = blockIdx.x * blockDim.x + tid;
        int n_agg4 = N * (D / 4);
        int stride = gridDim.x * blockDim.x;
        for (int i = gidx; i < n_agg4; i += stride)
            ((float4*)g_agg)[i] = make_float4(0.f, 0.f, 0.f, 0.f);
        for (int i = gidx; i < N; i += stride)
            g_cnt[i] = 0.f;
    }

#pragma unroll
    for (int q = 0; q < 4; q++) {
        int idx = tid + q * 256;
        int k = idx >> 4, j = idx & 15;
        wt[k][j] = (j < 8) ? g_w[j * 2 * D + k] : g_w[(j - 8) * 2 * D + D + k];
    }
    {
        int n = tid >> 4;
        int k0 = (tid & 15) * 4;
        int nn = min(base + n, N - 1);
        float4 v = __ldg((const float4*)(x + (size_t)nn * D + k0));
        xt[k0 + 0][n] = v.x; xt[k0 + 1][n] = v.y;
        xt[k0 + 2][n] = v.z; xt[k0 + 3][n] = v.w;
    }
    __syncthreads();

    int n = tid & 15, j = tid >> 4;
    float acc = 0.f;
#pragma unroll
    for (int k = 0; k < D; k++) acc += xt[k][n] * wt[k][j];

    int nn = base + n;
    if (nn < N) g_y[(size_t)nn * 16 + j] = acc;
}

// ---------------------------------------------------------------------------
// Kernel 3: edge phase v3. One edge PER LANE (32 edges/warp):
//   scalar phase (coalesced): idx loads, y loads, one sigmoid per edge, cnt RED
//   vector phase: for each edge j, shfl-broadcast (s,d,gate); 32 lanes
//     load x[s] as float2 (256B) and red.global.add.v2 into agg[d] (256B).
// ---------------------------------------------------------------------------
__global__ __launch_bounds__(256) void edge_kernel(
        const float* __restrict__ x,
        const int* __restrict__ src,
        const int* __restrict__ dst,
        const int* __restrict__ rel,
        int E) {
    int warp = (blockIdx.x * blockDim.x + threadIdx.x) >> 5;
    int lane = threadIdx.x & 31;

    int ew = warp * 32;              // first edge of this warp
    if (ew >= E) return;
    int ne = min(32, E - ew);

    // ---- scalar phase: one edge per lane ----
    int e = ew + min(lane, ne - 1);
    int s = __ldg(src + e);
    int d = __ldg(dst + e);
    int r = __ldg(rel + e);

    float yd = __ldg(g_y + (size_t)d * 16 + r);
    float ys = __ldg(g_y + (size_t)s * 16 + 8 + r);
    float gate = 1.0f / (1.0f + __expf(-(yd + ys)));

    if (lane < ne) atomicAdd(g_cnt + d, 1.0f);

    // ---- vector phase: broadcast each edge, all lanes gather + RED ----
    const float2* x2 = (const float2*)x;
    int j = 0;
    for (; j + 4 <= ne; j += 4) {
        int s0 = __shfl_sync(0xffffffffu, s, j + 0);
        int s1 = __shfl_sync(0xffffffffu, s, j + 1);
        int s2 = __shfl_sync(0xffffffffu, s, j + 2);
        int s3 = __shfl_sync(0xffffffffu, s, j + 3);
        int d0 = __shfl_sync(0xffffffffu, d, j + 0);
        int d1 = __shfl_sync(0xffffffffu, d, j + 1);
        int d2 = __shfl_sync(0xffffffffu, d, j + 2);
        int d3 = __shfl_sync(0xffffffffu, d, j + 3);
        float g0 = __shfl_sync(0xffffffffu, gate, j + 0);
        float g1 = __shfl_sync(0xffffffffu, gate, j + 1);
        float g2 = __shfl_sync(0xffffffffu, gate, j + 2);
        float g3 = __shfl_sync(0xffffffffu, gate, j + 3);

        float2 v0 = __ldg(x2 + (size_t)s0 * (D / 2) + lane);
        float2 v1 = __ldg(x2 + (size_t)s1 * (D / 2) + lane);
        float2 v2 = __ldg(x2 + (size_t)s2 * (D / 2) + lane);
        float2 v3 = __ldg(x2 + (size_t)s3 * (D / 2) + lane);

        float* a0 = g_agg + (size_t)d0 * D + lane * 2;
        float* a1 = g_agg + (size_t)d1 * D + lane * 2;
        float* a2 = g_agg + (size_t)d2 * D + lane * 2;
        float* a3 = g_agg + (size_t)d3 * D + lane * 2;
        asm volatile("red.global.add.v2.f32 [%0], {%1,%2};"
                     :: "l"(a0), "f"(v0.x * g0), "f"(v0.y * g0) : "memory");
        asm volatile("red.global.add.v2.f32 [%0], {%1,%2};"
                     :: "l"(a1), "f"(v1.x * g1), "f"(v1.y * g1) : "memory");
        asm volatile("red.global.add.v2.f32 [%0], {%1,%2};"
                     :: "l"(a2), "f"(v2.x * g2), "f"(v2.y * g2) : "memory");
        asm volatile("red.global.add.v2.f32 [%0], {%1,%2};"
                     :: "l"(a3), "f"(v3.x * g3), "f"(v3.y * g3) : "memory");
    }
    for (; j < ne; j++) {
        int sj = __shfl_sync(0xffffffffu, s, j);
        int dj = __shfl_sync(0xffffffffu, d, j);
        float gj = __shfl_sync(0xffffffffu, gate, j);
        float2 v = __ldg(x2 + (size_t)sj * (D / 2) + lane);
        float* a = g_agg + (size_t)dj * D + lane * 2;
        asm volatile("red.global.add.v2.f32 [%0], {%1,%2};"
                     :: "l"(a), "f"(v.x * gj), "f"(v.y * gj) : "memory");
    }
}

// ---------------------------------------------------------------------------
// Kernel 4: node GEMM (unchanged).
// ---------------------------------------------------------------------------
#define BN 64
#define KCH 64

__global__ __launch_bounds__(256, 3) void node_kernel(
        const float* __restrict__ x,
        const float* __restrict__ Wl,
        const float* __restrict__ b,
        float* __restrict__ out,
        int N) {
    __shared__ float csm[KCH][66];
    __shared__ float wsm[D][KCH];

    int tid = threadIdx.x;
    int tx = tid & 31;
    int ty = tid >> 5;
    int base = blockIdx.x * BN;

    float acc[2][8];
#pragma unroll
    for (int j = 0; j < 8; j++) {
        float bv = __ldg(b + ty * 8 + j);
        acc[0][j] = bv; acc[1][j] = bv;
    }

#pragma unroll
    for (int kc = 0; kc < 2; kc++) {
#pragma unroll
        for (int q = 0; q < 4; q++) {
            int idx = (tid + q * 256) * 4;
            int o = idx >> 6, k = idx & 63;
            float4 v = __ldg((const float4*)(Wl + (size_t)o * 2 * D + kc * KCH + k));
            *(float4*)&wsm[o][k] = v;
        }
        {
            int n = tid & 63;
            int q16 = tid >> 6;
            int k0 = q16 * 16;
            int nn = min(base + n, N - 1);
            const float4* srcp;
            float scale;
            if (kc == 0) {
                srcp = (const float4*)(x + (size_t)nn * D + k0);
                scale = 1.0f;
            } else {
                srcp = (const float4*)(g_agg + (size_t)nn * D + k0);
                scale = 1.0f / fmaxf(g_cnt[nn], 1.0f);
            }
#pragma unroll
            for (int q = 0; q < 4; q++) {
                float4 v = __ldg(srcp + q);
                int k = k0 + q * 4;
                csm[k + 0][n] = v.x * scale;
                csm[k + 1][n] = v.y * scale;
                csm[k + 2][n] = v.z * scale;
                csm[k + 3][n] = v.w * scale;
            }
        }
        __syncthreads();

#pragma unroll 8
        for (int k4 = 0; k4 < KCH; k4 += 4) {
            float4 w[8];
#pragma unroll
            for (int j = 0; j < 8; j++)
                w[j] = *(const float4*)&wsm[ty * 8 + j][k4];

            float2 c0 = *(const float2*)&csm[k4 + 0][tx * 2];
            float2 c1 = *(const float2*)&csm[k4 + 1][tx * 2];
            float2 c2 = *(const float2*)&csm[k4 + 2][tx * 2];
            float2 c3 = *(const float2*)&csm[k4 + 3][tx * 2];

#pragma unroll
            for (int j = 0; j < 8; j++) {
                acc[0][j] += c0.x * w[j].x; acc[1][j] += c0.y * w[j].x;
                acc[0][j] += c1.x * w[j].y; acc[1][j] += c1.y * w[j].y;
                acc[0][j] += c2.x * w[j].z; acc[1][j] += c2.y * w[j].z;
                acc[0][j] += c3.x * w[j].w; acc[1][j] += c3.y * w[j].w;
            }
        }
        __syncthreads();
    }

#pragma unroll
    for (int i = 0; i < 2; i++) {
        int n = base + tx * 2 + i;
        if (n < N) {
            float* op = out + (size_t)n * D + ty * 8;
            float4 r0, r1;
            r0.x = acc[i][0] > 0.f ? acc[i][0] : 0.01f * acc[i][0];
            r0.y = acc[i][1] > 0.f ? acc[i][1] : 0.01f * acc[i][1];
            r0.z = acc[i][2] > 0.f ? acc[i][2] : 0.01f * acc[i][2];
            r0.w = acc[i][3] > 0.f ? acc[i][3] : 0.01f * acc[i][3];
            r1.x = acc[i][4] > 0.f ? acc[i][4] : 0.01f * acc[i][4];
            r1.y = acc[i][5] > 0.f ? acc[i][5] : 0.01f * acc[i][5];
            r1.z = acc[i][6] > 0.f ? acc[i][6] : 0.01f * acc[i][6];
            r1.w = acc[i][7] > 0.f ? acc[i][7] : 0.01f * acc[i][7];
            *(float4*)op = r0;
            *(float4*)(op + 4) = r1;
        }
    }
}

// ---------------------------------------------------------------------------
extern "C" void kernel_launch(void* const* d_in, const int* in_sizes, int n_in,
                              void* d_out, int out_size) {
    const float* x    = (const float*)d_in[0];
    const int*   src  = (const int*)d_in[1];
    const int*   dst  = (const int*)d_in[2];
    const int*   rel  = (const int*)d_in[3];
    const float* W_r  = (const float*)d_in[4];
    const float* W_lin= (const float*)d_in[5];
    const float* b_lin= (const float*)d_in[6];
    float* out = (float*)d_out;

    int N = in_sizes[0] / D;     // 50000
    int E = in_sizes[1];         // 800000

    wsum_kernel<<<N_REL, 2 * D>>>(W_r);

    y_kernel<<<(N + 15) / 16, 256>>>(x, N);

    int ewarps = (E + 31) / 32;
    edge_kernel<<<(ewarps * 32 + 255) / 256, 256>>>(x, src, dst, rel, E);

    node_kernel<<<(N + BN - 1) / BN, 256>>>(x, W_lin, b_lin, out, N);
}